// round 14
// baseline (speedup 1.0000x reference)
#include <cuda_runtime.h>
#include <math.h>

#define TT 1500
#define BB 16
#define FF 440
#define HH 512
#define MM (TT*BB)      // 24000
#define NC 128          // persistent CTAs (single wave)

typedef unsigned long long ull;

// ---------------- device scratch (no allocations allowed) -------------------
__device__ float g_wh0[MM*HH];
__device__ float g_wz0[MM*HH];
__device__ float g_h1buf[4*BB*HH];   // 4-deep ring of h1 states
__device__ float g_h2buf[2*BB*HH];   // 2-deep ring of h2 states
__device__ unsigned g_cA, g_cB;      // zero-init arrival counters (monotonic)
__device__ unsigned g_genA, g_genB;  // zero-init generation flags (monotonic)

// ---------------- helpers ----------------------------------------------------
__device__ __forceinline__ unsigned ld_acq(const unsigned* p) {
    unsigned v;
    asm volatile("ld.acquire.gpu.u32 %0, [%1];" : "=r"(v) : "l"(p) : "memory");
    return v;
}
__device__ __forceinline__ void st_rel(unsigned* p, unsigned v) {
    asm volatile("st.release.gpu.u32 [%0], %1;" :: "l"(p), "r"(v) : "memory");
}
__device__ __forceinline__ void fma2(ull &d, ull a, ull b) {
    asm("fma.rn.f32x2 %0, %1, %2, %0;" : "+l"(d) : "l"(a), "l"(b));
}
__device__ __forceinline__ void unpack2(ull v, float &lo, float &hi) {
    asm("mov.b64 {%0, %1}, %2;" : "=f"(lo), "=f"(hi) : "l"(v));
}
#define BAR1() asm volatile("bar.sync 1, 128;" ::: "memory")
#define BAR2() asm volatile("bar.sync 2, 128;" ::: "memory")

// fold-reduce 32 values over 32 lanes: lane L ends with full sum of v[L].
__device__ __forceinline__ float warp_fold32(const float* v, int lane) {
    float a[16];
    { bool hi = (lane & 16) != 0;
      #pragma unroll
      for (int i = 0; i < 16; ++i) {
          float s = hi ? v[i] : v[i+16];
          float k = hi ? v[i+16] : v[i];
          a[i] = k + __shfl_xor_sync(0xffffffffu, s, 16); } }
    float b[8];
    { bool hi = (lane & 8) != 0;
      #pragma unroll
      for (int i = 0; i < 8; ++i) {
          float s = hi ? a[i] : a[i+8];
          float k = hi ? a[i+8] : a[i];
          b[i] = k + __shfl_xor_sync(0xffffffffu, s, 8); } }
    float c[4];
    { bool hi = (lane & 4) != 0;
      #pragma unroll
      for (int i = 0; i < 4; ++i) {
          float s = hi ? b[i] : b[i+4];
          float k = hi ? b[i+4] : b[i];
          c[i] = k + __shfl_xor_sync(0xffffffffu, s, 4); } }
    float d[2];
    { bool hi = (lane & 2) != 0;
      #pragma unroll
      for (int i = 0; i < 2; ++i) {
          float s = hi ? c[i] : c[i+2];
          float k = hi ? c[i+2] : c[i];
          d[i] = k + __shfl_xor_sync(0xffffffffu, s, 2); } }
    float e;
    { bool hi = (lane & 1) != 0;
      float s = hi ? d[0] : d[1];
      float k = hi ? d[1] : d[0];
      e = k + __shfl_xor_sync(0xffffffffu, s, 1); }
    return e;
}

// ---------------- projection GEMM: C[M,512] = A[M,K] @ W[512,K]^T + bias ----
__global__ void __launch_bounds__(256) gemm512(
    const float* __restrict__ A,
    const float* __restrict__ W, const float* __restrict__ bias,
    int out_sel, int K)
{
    float* C = out_sel ? g_wz0 : g_wh0;

    __shared__ __align__(16) float As[8][64];
    __shared__ __align__(16) float Bs[8][64];

    int tid = threadIdx.x;
    int m0 = blockIdx.x * 64, n0 = blockIdx.y * 64;
    int lr = tid >> 2;
    int lk = (tid & 3) * 2;
    const float* ap = A + (size_t)(m0 + lr) * K + lk;
    const float* wp = W + (size_t)(n0 + lr) * K + lk;
    int ty = tid >> 4, tx = tid & 15;

    float acc[4][4] = {};
    int nkb = K / 8;
    for (int kb = 0; kb < nkb; ++kb) {
        float2 av = *(const float2*)ap;
        float2 wv = *(const float2*)wp;
        ap += 8; wp += 8;
        As[lk][lr] = av.x; As[lk+1][lr] = av.y;
        Bs[lk][lr] = wv.x; Bs[lk+1][lr] = wv.y;
        __syncthreads();
        #pragma unroll
        for (int k = 0; k < 8; ++k) {
            float4 a4 = *(const float4*)&As[k][ty*4];
            float4 b4 = *(const float4*)&Bs[k][tx*4];
            float a_[4] = {a4.x, a4.y, a4.z, a4.w};
            float b_[4] = {b4.x, b4.y, b4.z, b4.w};
            #pragma unroll
            for (int i = 0; i < 4; ++i)
                #pragma unroll
                for (int j = 0; j < 4; ++j)
                    acc[i][j] += a_[i] * b_[j];
        }
        __syncthreads();
    }
    #pragma unroll
    for (int i = 0; i < 4; ++i) {
        float4 o;
        o.x = acc[i][0] + bias[n0 + tx*4 + 0];
        o.y = acc[i][1] + bias[n0 + tx*4 + 1];
        o.z = acc[i][2] + bias[n0 + tx*4 + 2];
        o.w = acc[i][3] + bias[n0 + tx*4 + 3];
        *(float4*)&C[(size_t)(m0 + ty*4 + i) * HH + n0 + tx*4] = o;
    }
}

// ---------------- fused persistent 2-layer, warp-specialized -----------------
// Warps 0-3: layer-1 loop (t = 0..TT-1), flag genA, named barrier 1.
// Warps 4-7: layer-2 loop (t = 1..TT, computing step t-1), flag genB, barrier 2.
// CTA owns columns j0..j0+3 of both layers.
// L1 warp = (gate, batch-octet): 4 rows x 8 batches, U0 slice in registers.
// L2 warp = (batch-octet, gate): W1/U1 slices in smem.
__global__ void __launch_bounds__(256, 1) fused(
    const float* __restrict__ Uh0, const float* __restrict__ Uz0,
    const float* __restrict__ Uh1, const float* __restrict__ Uz1,
    const float* __restrict__ Wh1, const float* __restrict__ Wz1,
    const float* __restrict__ bh1, const float* __restrict__ bz1,
    float* __restrict__ out)
{
    extern __shared__ float sm[];
    float* h1sA = sm;            // 8192 f : L1 group's copy of h1[t-1]
    float* h1sB = sm + 8192;     // 8192 f : L2 group's copy of h1[t-1]
    float* h2s  = sm + 16384;    // 8192 f : h2[t-2]
    float* w1s  = sm + 24576;    // 4096 f : [gate][4 rows][512] of Wz1/Wh1
    float* u1s  = sm + 28672;    // 4096 f : [gate][4 rows][512] of Uz1/Uh1
    float* sdA  = sm + 32768;    // 128 f  : L1 dots  [gate][b][j]
    float* sdP  = sm + 32896;    // 128 f  : L2 proj  dots
    float* sdQ  = sm + 33024;    // 128 f  : L2 recur dots
    __shared__ unsigned s_baseA, s_baseB;

    int tid  = threadIdx.x;
    int lane = tid & 31;
    int j0   = blockIdx.x * 4;
    int k0   = lane * 2;

    if (tid == 0) {
        s_baseA = ld_acq(&g_genA);
        s_baseB = ld_acq(&g_genB);
    }

    // load layer-2 weight slices into smem (both gates)
    for (int q = tid; q < 1024; q += 256) {
        int g = q >> 9, r = (q >> 7) & 3, kk = (q & 127) * 4;
        const float* Wp = g ? Wh1 : Wz1;
        const float* Up = g ? Uh1 : Uz1;
        ((float4*)w1s)[q] = *(const float4*)&Wp[(size_t)(j0 + r) * HH + kk];
        ((float4*)u1s)[q] = *(const float4*)&Up[(size_t)(j0 + r) * HH + kk];
    }
    __syncthreads();
    unsigned baseA = s_baseA, baseB = s_baseB;

    if (tid < 128) {
        // ==================== LAYER-1 GROUP ====================
        int w = tid >> 5;          // 0..3
        int g = w >> 1, oct = w & 1;
        const float* U0 = g ? Uh0 : Uz0;
        ull U0r[4][8];
        #pragma unroll
        for (int r = 0; r < 4; ++r)
            #pragma unroll
            for (int i = 0; i < 8; ++i)
                U0r[r][i] = *(const ull*)&U0[(size_t)(j0 + r) * HH + k0 + 64*i];

        int gb = tid >> 2, gr = tid & 3;     // gate threads: tid < 64
        float wzv = 0.f, whv = 0.f;
        int ob = gb * HH + j0 + gr;
        if (tid < 64) {
            wzv = __ldcg(&g_wz0[ob]);
            whv = __ldcg(&g_wh0[ob]);
        }

        for (int t = 0; t < TT; ++t) {
            if (tid == 0) {
                if (t > 0) {
                    unsigned tg = baseA + (unsigned)t;
                    while ((int)(ld_acq(&g_genA) - tg) < 0) { }
                }
                if (t >= 4) {   // L2 may lag at most 3 steps (4-deep h1 ring)
                    unsigned tg = baseB + (unsigned)(t - 3);
                    while ((int)(ld_acq(&g_genB) - tg) < 0) { }
                }
            }
            BAR1();
            // stage h1[t-1]
            if (t == 0) {
                for (int f = tid; f < 2048; f += 128)
                    ((float4*)h1sA)[f] = make_float4(0.f,0.f,0.f,0.f);
            } else {
                const float4* s1 = (const float4*)(g_h1buf + (size_t)((t-1)&3) * BB * HH);
                #pragma unroll
                for (int q = 0; q < 16; ++q)
                    ((float4*)h1sA)[tid + q*128] = __ldcg(s1 + tid + q*128);
            }
            BAR1();
            // dots: 4 rows x 8 batches for (gate g, octet oct)
            {
                ull acc2[4][8];
                #pragma unroll
                for (int r = 0; r < 4; ++r)
                    #pragma unroll
                    for (int b = 0; b < 8; ++b) acc2[r][b] = 0ull;
                const float* hb = h1sA + (size_t)oct * 8 * HH;
                #pragma unroll
                for (int i = 0; i < 8; ++i) {
                    int k = k0 + 64*i;
                    ull hv[8];
                    #pragma unroll
                    for (int b = 0; b < 8; ++b) hv[b] = *(const ull*)&hb[b*HH + k];
                    #pragma unroll
                    for (int r = 0; r < 4; ++r)
                        #pragma unroll
                        for (int b = 0; b < 8; ++b)
                            fma2(acc2[r][b], U0r[r][i], hv[b]);
                }
                float v32[32];
                #pragma unroll
                for (int r = 0; r < 4; ++r)
                    #pragma unroll
                    for (int b = 0; b < 8; ++b) {
                        float lo, hi; unpack2(acc2[r][b], lo, hi);
                        v32[r*8 + b] = lo + hi;
                    }
                float s = warp_fold32(v32, lane);
                // lane L holds sum for row = L>>3, batch-in-octet = L&7
                sdA[g*64 + (oct*8 + (lane & 7))*4 + (lane >> 3)] = s;
            }
            BAR1();
            if (tid < 64) {
                float z  = 1.f / (1.f + __expf(-(wzv + sdA[gb*4 + gr])));
                float hc = whv + sdA[64 + gb*4 + gr];
                hc = hc > 0.f ? hc : 0.f;
                float h1n = z * h1sA[gb*HH + j0 + gr] + (1.f - z) * hc;
                g_h1buf[(size_t)(t & 3) * BB * HH + gb*HH + j0 + gr] = h1n;
                if (t + 1 < TT) {
                    ob += BB * HH;
                    wzv = __ldcg(&g_wz0[ob]);
                    whv = __ldcg(&g_wh0[ob]);
                }
            }
            BAR1();
            if (tid == 0) {
                __threadfence();
                unsigned old = atomicAdd(&g_cA, 1u);
                if (old + 1u == (baseA + (unsigned)t + 1u) * NC)
                    st_rel(&g_genA, baseA + (unsigned)t + 1u);
            }
        }
    } else {
        // ==================== LAYER-2 GROUP ====================
        int tl = tid - 128;        // 0..127
        int w = tl >> 5;           // 0..3
        int bgp = w >> 1, rg = w & 1;
        int gb = tl >> 2, gr = tl & 3;   // gate threads: tl < 64
        float bz1v = 0.f, bh1v = 0.f;
        if (tl < 64) {
            bz1v = bz1[j0 + gr];
            bh1v = bh1[j0 + gr];
        }

        for (int t = 1; t <= TT; ++t) {
            if (tid == 128) {
                {
                    unsigned tg = baseA + (unsigned)t;   // h1[t-1] written
                    while ((int)(ld_acq(&g_genA) - tg) < 0) { }
                }
                if (t >= 2) {
                    unsigned tg = baseB + (unsigned)(t - 1);  // h2[t-2] written
                    while ((int)(ld_acq(&g_genB) - tg) < 0) { }
                }
            }
            BAR2();
            // stage h1[t-1] (own copy) and h2[t-2]
            {
                const float4* s1 = (const float4*)(g_h1buf + (size_t)((t-1)&3) * BB * HH);
                #pragma unroll
                for (int q = 0; q < 16; ++q)
                    ((float4*)h1sB)[tl + q*128] = __ldcg(s1 + tl + q*128);
            }
            if (t == 1) {
                for (int f = tl; f < 2048; f += 128)
                    ((float4*)h2s)[f] = make_float4(0.f,0.f,0.f,0.f);
            } else {
                const float4* s2 = (const float4*)(g_h2buf + (size_t)(t & 1) * BB * HH);
                #pragma unroll
                for (int q = 0; q < 16; ++q)
                    ((float4*)h2s)[tl + q*128] = __ldcg(s2 + tl + q*128);
            }
            BAR2();
            // proj dots: gate rg over h1[t-1], batches octet bgp
            {
                ull acc2[4][8];
                #pragma unroll
                for (int r = 0; r < 4; ++r)
                    #pragma unroll
                    for (int b = 0; b < 8; ++b) acc2[r][b] = 0ull;
                const float* wb = w1s + rg * 2048;
                const float* hb = h1sB + (size_t)bgp * 8 * HH;
                #pragma unroll
                for (int i = 0; i < 8; ++i) {
                    int k = k0 + 64*i;
                    ull wv[4], hv[8];
                    #pragma unroll
                    for (int r = 0; r < 4; ++r) wv[r] = *(const ull*)&wb[r*HH + k];
                    #pragma unroll
                    for (int b = 0; b < 8; ++b) hv[b] = *(const ull*)&hb[b*HH + k];
                    #pragma unroll
                    for (int r = 0; r < 4; ++r)
                        #pragma unroll
                        for (int b = 0; b < 8; ++b)
                            fma2(acc2[r][b], wv[r], hv[b]);
                }
                float v32[32];
                #pragma unroll
                for (int r = 0; r < 4; ++r)
                    #pragma unroll
                    for (int b = 0; b < 8; ++b) {
                        float lo, hi; unpack2(acc2[r][b], lo, hi);
                        v32[r*8 + b] = lo + hi;
                    }
                float s = warp_fold32(v32, lane);
                sdP[rg*64 + (bgp*8 + (lane & 7))*4 + (lane >> 3)] = s;
            }
            // recur dots: gate rg over h2[t-2]
            {
                ull acc2[4][8];
                #pragma unroll
                for (int r = 0; r < 4; ++r)
                    #pragma unroll
                    for (int b = 0; b < 8; ++b) acc2[r][b] = 0ull;
                const float* wb = u1s + rg * 2048;
                const float* hb = h2s + (size_t)bgp * 8 * HH;
                #pragma unroll
                for (int i = 0; i < 8; ++i) {
                    int k = k0 + 64*i;
                    ull wv[4], hv[8];
                    #pragma unroll
                    for (int r = 0; r < 4; ++r) wv[r] = *(const ull*)&wb[r*HH + k];
                    #pragma unroll
                    for (int b = 0; b < 8; ++b) hv[b] = *(const ull*)&hb[b*HH + k];
                    #pragma unroll
                    for (int r = 0; r < 4; ++r)
                        #pragma unroll
                        for (int b = 0; b < 8; ++b)
                            fma2(acc2[r][b], wv[r], hv[b]);
                }
                float v32[32];
                #pragma unroll
                for (int r = 0; r < 4; ++r)
                    #pragma unroll
                    for (int b = 0; b < 8; ++b) {
                        float lo, hi; unpack2(acc2[r][b], lo, hi);
                        v32[r*8 + b] = lo + hi;
                    }
                float s = warp_fold32(v32, lane);
                sdQ[rg*64 + (bgp*8 + (lane & 7))*4 + (lane >> 3)] = s;
            }
            BAR2();
            if (tl < 64) {
                float zp  = 1.f / (1.f + __expf(-(bz1v + sdP[gb*4 + gr] + sdQ[gb*4 + gr])));
                float hcp = bh1v + sdP[64 + gb*4 + gr] + sdQ[64 + gb*4 + gr];
                hcp = hcp > 0.f ? hcp : 0.f;
                float h2n = zp * h2s[gb*HH + j0 + gr] + (1.f - zp) * hcp;
                g_h2buf[(size_t)((t-1) & 1) * BB * HH + gb*HH + j0 + gr] = h2n;
                out[(size_t)((t-1)*BB + gb) * HH + j0 + gr] = h2n;
            }
            BAR2();
            if (tid == 128) {
                __threadfence();
                unsigned old = atomicAdd(&g_cB, 1u);
                if (old + 1u == (baseB + (unsigned)t) * NC)
                    st_rel(&g_genB, baseB + (unsigned)t);
            }
        }
    }
}

// ---------------- launch ----------------------------------------------------
#define FUSED_SMEM ((33280) * 4)

extern "C" void kernel_launch(void* const* d_in, const int* in_sizes, int n_in,
                              void* d_out, int out_size) {
    const float* x   = (const float*)d_in[0];
    const float* Wh0 = (const float*)d_in[1];
    const float* bh0 = (const float*)d_in[2];
    const float* Wz0 = (const float*)d_in[3];
    const float* bz0 = (const float*)d_in[4];
    const float* Uh0 = (const float*)d_in[5];
    const float* Uz0 = (const float*)d_in[6];
    const float* Wh1 = (const float*)d_in[7];
    const float* bh1 = (const float*)d_in[8];
    const float* Wz1 = (const float*)d_in[9];
    const float* bz1 = (const float*)d_in[10];
    const float* Uh1 = (const float*)d_in[11];
    const float* Uz1 = (const float*)d_in[12];
    float* out = (float*)d_out;

    cudaFuncSetAttribute(fused, cudaFuncAttributeMaxDynamicSharedMemorySize,
                         FUSED_SMEM);

    dim3 gg(MM / 64, HH / 64);
    gemm512<<<gg, 256>>>(x, Wh0, bh0, 0, FF);
    gemm512<<<gg, 256>>>(x, Wz0, bz0, 1, FF);
    fused<<<NC, 256, FUSED_SMEM>>>(Uh0, Uz0, Uh1, Uz1, Wh1, Wz1, bh1, bz1, out);
}

// round 16
// speedup vs baseline: 1.1790x; 1.1790x over previous
#include <cuda_runtime.h>
#include <math.h>

#define TT 1500
#define BB 16
#define FF 440
#define HH 512
#define MM (TT*BB)      // 24000
#define NC 128          // persistent CTAs (single wave)

typedef unsigned long long ull;

// ---------------- device scratch (no allocations allowed) -------------------
__device__ float g_wh0[MM*HH];
__device__ float g_wz0[MM*HH];
__device__ float g_h1buf[2*BB*HH];
__device__ float g_h2buf[2*BB*HH];
__device__ unsigned g_cA, g_cB;      // zero-init arrival counters (monotonic)
__device__ unsigned g_genA, g_genB;  // zero-init generation flags (monotonic)

// ---------------- helpers ----------------------------------------------------
__device__ __forceinline__ unsigned ld_acq(const unsigned* p) {
    unsigned v;
    asm volatile("ld.acquire.gpu.u32 %0, [%1];" : "=r"(v) : "l"(p) : "memory");
    return v;
}
__device__ __forceinline__ void st_rel(unsigned* p, unsigned v) {
    asm volatile("st.release.gpu.u32 [%0], %1;" :: "l"(p), "r"(v) : "memory");
}
__device__ __forceinline__ void fma2(ull &d, ull a, ull b) {
    asm("fma.rn.f32x2 %0, %1, %2, %0;" : "+l"(d) : "l"(a), "l"(b));
}
__device__ __forceinline__ void unpack2(ull v, float &lo, float &hi) {
    asm("mov.b64 {%0, %1}, %2;" : "=f"(lo), "=f"(hi) : "l"(v));
}

// fold-reduce 16 values over 32 lanes: every lane ends with the full 32-lane
// sum of v16[(lane>>1)&15].
__device__ __forceinline__ float warp_fold16(const float v16[16], int lane) {
    float v8[8];
    { bool hi = (lane & 16) != 0;
      #pragma unroll
      for (int i = 0; i < 8; ++i) {
          float s = hi ? v16[i] : v16[i+8];
          float k = hi ? v16[i+8] : v16[i];
          v8[i] = k + __shfl_xor_sync(0xffffffffu, s, 16); } }
    float v4[4];
    { bool hi = (lane & 8) != 0;
      #pragma unroll
      for (int i = 0; i < 4; ++i) {
          float s = hi ? v8[i] : v8[i+4];
          float k = hi ? v8[i+4] : v8[i];
          v4[i] = k + __shfl_xor_sync(0xffffffffu, s, 8); } }
    float v2[2];
    { bool hi = (lane & 4) != 0;
      #pragma unroll
      for (int i = 0; i < 2; ++i) {
          float s = hi ? v4[i] : v4[i+2];
          float k = hi ? v4[i+2] : v4[i];
          v2[i] = k + __shfl_xor_sync(0xffffffffu, s, 4); } }
    float v1;
    { bool hi = (lane & 2) != 0;
      float s = hi ? v2[0] : v2[1];
      float k = hi ? v2[1] : v2[0];
      v1 = k + __shfl_xor_sync(0xffffffffu, s, 2); }
    v1 += __shfl_xor_sync(0xffffffffu, v1, 1);
    return v1;
}

// ---------------- projection GEMM: C[M,512] = A[M,K] @ W[512,K]^T + bias ----
__global__ void __launch_bounds__(256) gemm512(
    const float* __restrict__ A,
    const float* __restrict__ W, const float* __restrict__ bias,
    int out_sel, int K)
{
    float* C = out_sel ? g_wz0 : g_wh0;

    __shared__ __align__(16) float As[8][64];
    __shared__ __align__(16) float Bs[8][64];

    int tid = threadIdx.x;
    int m0 = blockIdx.x * 64, n0 = blockIdx.y * 64;
    int lr = tid >> 2;
    int lk = (tid & 3) * 2;
    const float* ap = A + (size_t)(m0 + lr) * K + lk;
    const float* wp = W + (size_t)(n0 + lr) * K + lk;
    int ty = tid >> 4, tx = tid & 15;

    float acc[4][4] = {};
    int nkb = K / 8;
    for (int kb = 0; kb < nkb; ++kb) {
        float2 av = *(const float2*)ap;
        float2 wv = *(const float2*)wp;
        ap += 8; wp += 8;
        As[lk][lr] = av.x; As[lk+1][lr] = av.y;
        Bs[lk][lr] = wv.x; Bs[lk+1][lr] = wv.y;
        __syncthreads();
        #pragma unroll
        for (int k = 0; k < 8; ++k) {
            float4 a4 = *(const float4*)&As[k][ty*4];
            float4 b4 = *(const float4*)&Bs[k][tx*4];
            float a_[4] = {a4.x, a4.y, a4.z, a4.w};
            float b_[4] = {b4.x, b4.y, b4.z, b4.w};
            #pragma unroll
            for (int i = 0; i < 4; ++i)
                #pragma unroll
                for (int j = 0; j < 4; ++j)
                    acc[i][j] += a_[i] * b_[j];
        }
        __syncthreads();
    }
    #pragma unroll
    for (int i = 0; i < 4; ++i) {
        float4 o;
        o.x = acc[i][0] + bias[n0 + tx*4 + 0];
        o.y = acc[i][1] + bias[n0 + tx*4 + 1];
        o.z = acc[i][2] + bias[n0 + tx*4 + 2];
        o.w = acc[i][3] + bias[n0 + tx*4 + 3];
        *(float4*)&C[(size_t)(m0 + ty*4 + i) * HH + n0 + tx*4] = o;
    }
}

// ---------------- fused persistent 2-layer, split-flag loose coupling --------
// iter t: A-phase = layer1 step t (publish genA right after h1[t] store);
//         B-phase = layer2 step t-1 (publish genB after h2[t-1] store).
// Steady state: waits are satisfied ~one opposite-phase ago -> barrier latency
// and jitter hide in slack. All 256 threads run both phases.
// CTA owns columns j0..j0+3 of both layers. Warp w: bg=w>>1 (4 batches),
// rg=w&1 (0 = z gate, 1 = h gate). lane covers k-pairs k0 = lane*2 + 64*i.
__global__ void __launch_bounds__(256, 1) fused(
    const float* __restrict__ Uh0, const float* __restrict__ Uz0,
    const float* __restrict__ Uh1, const float* __restrict__ Uz1,
    const float* __restrict__ Wh1, const float* __restrict__ Wz1,
    const float* __restrict__ bh1, const float* __restrict__ bz1,
    float* __restrict__ out)
{
    extern __shared__ float sm[];
    float* h1s = sm;                 // 8192 f : h1[t-1]
    float* h2s = sm + 8192;          // 8192 f : h2[t-2]
    float* w1s = sm + 16384;         // 4096 f : [gate][4 rows][512] Wz1/Wh1
    float* u1s = sm + 20480;         // 4096 f : [gate][4 rows][512] Uz1/Uh1
    float* sdA = sm + 24576;         // 128 f  : L1 dots [gate][b][r]
    float* sdP = sm + 24704;         // 128 f  : L2 combined dots
    __shared__ unsigned s_baseA, s_baseB;

    int tid = threadIdx.x, w = tid >> 5, lane = tid & 31;
    int bg = w >> 1, rg = w & 1;
    int j0 = blockIdx.x * 4;
    int k0 = lane * 2;

    if (tid == 0) {
        s_baseA = ld_acq(&g_genA);
        s_baseB = ld_acq(&g_genB);
    }

    // layer-1 U slice in registers
    const float* U0 = rg ? Uh0 : Uz0;
    ull U0r[4][8];
    #pragma unroll
    for (int r = 0; r < 4; ++r)
        #pragma unroll
        for (int i = 0; i < 8; ++i)
            U0r[r][i] = *(const ull*)&U0[(size_t)(j0 + r) * HH + k0 + 64*i];

    // layer-2 weight slices into smem (persistent)
    for (int q = tid; q < 1024; q += 256) {
        int g = q >> 9, r = (q >> 7) & 3, kk = (q & 127) * 4;
        const float* Wp = g ? Wh1 : Wz1;
        const float* Up = g ? Uh1 : Uz1;
        ((float4*)w1s)[q] = *(const float4*)&Wp[(size_t)(j0 + r) * HH + kk];
        ((float4*)u1s)[q] = *(const float4*)&Up[(size_t)(j0 + r) * HH + kk];
    }
    __syncthreads();
    unsigned baseA = s_baseA, baseB = s_baseB;

    int gb = tid >> 2, gr = tid & 3;     // gate threads: tid < 64
    float wzv = 0.f, whv = 0.f, bh1v = 0.f, bz1v = 0.f;
    int ob = gb * HH + j0 + gr;
    if (tid < 64) {
        wzv  = __ldcg(&g_wz0[ob]);
        whv  = __ldcg(&g_wh0[ob]);
        bz1v = bz1[j0 + gr];
        bh1v = bh1[j0 + gr];
    }

    for (int t = 0; t <= TT; ++t) {
        // ================= A phase: layer-1 step t =================
        if (t > 0 && tid == 0) {
            unsigned tg = baseA + (unsigned)t;
            while ((int)(ld_acq(&g_genA) - tg) < 0) { }
        }
        __syncthreads();
        if (t == 0) {
            for (int f = tid; f < 2048; f += 256)
                ((float4*)h1s)[f] = make_float4(0.f,0.f,0.f,0.f);
        } else {
            const float4* s1 = (const float4*)(g_h1buf + (size_t)((t-1)&1) * BB * HH);
            #pragma unroll
            for (int q = 0; q < 8; ++q)
                ((float4*)h1s)[tid + q*256] = __ldcg(s1 + tid + q*256);
        }
        __syncthreads();

        if (t < TT) {
            // L1 dots: 4 rows x 4 batches, U0 in registers
            ull acc2[16];
            #pragma unroll
            for (int j = 0; j < 16; ++j) acc2[j] = 0ull;
            const float* hb = h1s + (size_t)bg * 4 * HH;
            #pragma unroll
            for (int i = 0; i < 8; ++i) {
                int k = k0 + 64*i;
                ull h0 = *(const ull*)&hb[k];
                ull h1 = *(const ull*)&hb[HH + k];
                ull h2 = *(const ull*)&hb[2*HH + k];
                ull h3 = *(const ull*)&hb[3*HH + k];
                #pragma unroll
                for (int r = 0; r < 4; ++r) {
                    fma2(acc2[r*4+0], U0r[r][i], h0);
                    fma2(acc2[r*4+1], U0r[r][i], h1);
                    fma2(acc2[r*4+2], U0r[r][i], h2);
                    fma2(acc2[r*4+3], U0r[r][i], h3);
                }
            }
            float val[16];
            #pragma unroll
            for (int j = 0; j < 16; ++j) {
                float lo, hi; unpack2(acc2[j], lo, hi);
                val[j] = lo + hi;
            }
            float s = warp_fold16(val, lane);
            int v = (lane >> 1) & 15;
            if (!(lane & 1))
                sdA[rg*64 + (bg*4 + (v&3))*4 + (v>>2)] = s;
            __syncthreads();
            if (tid < 64) {
                float z  = 1.f / (1.f + __expf(-(wzv + sdA[gb*4 + gr])));
                float hc = whv + sdA[64 + gb*4 + gr];
                hc = hc > 0.f ? hc : 0.f;
                float h1n = z * h1s[gb*HH + j0 + gr] + (1.f - z) * hc;
                g_h1buf[(size_t)(t&1) * BB * HH + gb*HH + j0 + gr] = h1n;
                if (t + 1 < TT) {      // prefetch next projections (overlaps B)
                    ob += BB * HH;
                    wzv = __ldcg(&g_wz0[ob]);
                    whv = __ldcg(&g_wh0[ob]);
                }
            }
            __syncthreads();
            if (tid == 0) {
                __threadfence();
                unsigned old = atomicAdd(&g_cA, 1u);
                if (old + 1u == (baseA + (unsigned)t + 1u) * NC)
                    st_rel(&g_genA, baseA + (unsigned)t + 1u);
            }
        }

        // ================= B phase: layer-2 step t-1 =================
        if (t >= 1) {
            if (t >= 2 && tid == 0) {
                unsigned tg = baseB + (unsigned)(t - 1);
                while ((int)(ld_acq(&g_genB) - tg) < 0) { }
            }
            __syncthreads();
            if (t == 1) {
                for (int f = tid; f < 2048; f += 256)
                    ((float4*)h2s)[f] = make_float4(0.f,0.f,0.f,0.f);
            } else {
                const float4* s2 = (const float4*)(g_h2buf + (size_t)(t&1) * BB * HH);
                #pragma unroll
                for (int q = 0; q < 8; ++q)
                    ((float4*)h2s)[tid + q*256] = __ldcg(s2 + tid + q*256);
            }
            __syncthreads();

            // combined L2 dots: proj over h1[t-1] (W1) + recur over h2[t-2] (U1)
            ull acc2[16];
            #pragma unroll
            for (int j = 0; j < 16; ++j) acc2[j] = 0ull;
            const float* wb  = w1s + rg * 2048;
            const float* ub  = u1s + rg * 2048;
            const float* hb1 = h1s + (size_t)bg * 4 * HH;
            const float* hb2 = h2s + (size_t)bg * 4 * HH;
            #pragma unroll
            for (int i = 0; i < 8; ++i) {
                int k = k0 + 64*i;
                ull wv0 = *(const ull*)&wb[k];
                ull wv1 = *(const ull*)&wb[HH + k];
                ull wv2 = *(const ull*)&wb[2*HH + k];
                ull wv3 = *(const ull*)&wb[3*HH + k];
                ull h0 = *(const ull*)&hb1[k];
                ull h1 = *(const ull*)&hb1[HH + k];
                ull h2 = *(const ull*)&hb1[2*HH + k];
                ull h3 = *(const ull*)&hb1[3*HH + k];
                fma2(acc2[0],  wv0, h0); fma2(acc2[1],  wv0, h1);
                fma2(acc2[2],  wv0, h2); fma2(acc2[3],  wv0, h3);
                fma2(acc2[4],  wv1, h0); fma2(acc2[5],  wv1, h1);
                fma2(acc2[6],  wv1, h2); fma2(acc2[7],  wv1, h3);
                fma2(acc2[8],  wv2, h0); fma2(acc2[9],  wv2, h1);
                fma2(acc2[10], wv2, h2); fma2(acc2[11], wv2, h3);
                fma2(acc2[12], wv3, h0); fma2(acc2[13], wv3, h1);
                fma2(acc2[14], wv3, h2); fma2(acc2[15], wv3, h3);
            }
            #pragma unroll
            for (int i = 0; i < 8; ++i) {
                int k = k0 + 64*i;
                ull wv0 = *(const ull*)&ub[k];
                ull wv1 = *(const ull*)&ub[HH + k];
                ull wv2 = *(const ull*)&ub[2*HH + k];
                ull wv3 = *(const ull*)&ub[3*HH + k];
                ull h0 = *(const ull*)&hb2[k];
                ull h1 = *(const ull*)&hb2[HH + k];
                ull h2 = *(const ull*)&hb2[2*HH + k];
                ull h3 = *(const ull*)&hb2[3*HH + k];
                fma2(acc2[0],  wv0, h0); fma2(acc2[1],  wv0, h1);
                fma2(acc2[2],  wv0, h2); fma2(acc2[3],  wv0, h3);
                fma2(acc2[4],  wv1, h0); fma2(acc2[5],  wv1, h1);
                fma2(acc2[6],  wv1, h2); fma2(acc2[7],  wv1, h3);
                fma2(acc2[8],  wv2, h0); fma2(acc2[9],  wv2, h1);
                fma2(acc2[10], wv2, h2); fma2(acc2[11], wv2, h3);
                fma2(acc2[12], wv3, h0); fma2(acc2[13], wv3, h1);
                fma2(acc2[14], wv3, h2); fma2(acc2[15], wv3, h3);
            }
            float val[16];
            #pragma unroll
            for (int j = 0; j < 16; ++j) {
                float lo, hi; unpack2(acc2[j], lo, hi);
                // acc2 index = r*4 + b; val layout must match fold writer (r*4+b)
                val[j] = lo + hi;
            }
            float s = warp_fold16(val, lane);
            int v = (lane >> 1) & 15;
            if (!(lane & 1))
                sdP[rg*64 + (bg*4 + (v&3))*4 + (v>>2)] = s;
            __syncthreads();
            if (tid < 64) {
                float zp  = 1.f / (1.f + __expf(-(bz1v + sdP[gb*4 + gr])));
                float hcp = bh1v + sdP[64 + gb*4 + gr];
                hcp = hcp > 0.f ? hcp : 0.f;
                float h2n = zp * h2s[gb*HH + j0 + gr] + (1.f - zp) * hcp;
                g_h2buf[(size_t)((t-1)&1) * BB * HH + gb*HH + j0 + gr] = h2n;
                out[(size_t)((t-1)*BB + gb) * HH + j0 + gr] = h2n;
            }
            __syncthreads();
            if (tid == 0) {
                __threadfence();
                unsigned old = atomicAdd(&g_cB, 1u);
                if (old + 1u == (baseB + (unsigned)t) * NC)
                    st_rel(&g_genB, baseB + (unsigned)t);
            }
        }
    }
}

// ---------------- launch ----------------------------------------------------
#define FUSED_SMEM ((24832) * 4)

extern "C" void kernel_launch(void* const* d_in, const int* in_sizes, int n_in,
                              void* d_out, int out_size) {
    const float* x   = (const float*)d_in[0];
    const float* Wh0 = (const float*)d_in[1];
    const float* bh0 = (const float*)d_in[2];
    const float* Wz0 = (const float*)d_in[3];
    const float* bz0 = (const float*)d_in[4];
    const float* Uh0 = (const float*)d_in[5];
    const float* Uz0 = (const float*)d_in[6];
    const float* Wh1 = (const float*)d_in[7];
    const float* bh1 = (const float*)d_in[8];
    const float* Wz1 = (const float*)d_in[9];
    const float* bz1 = (const float*)d_in[10];
    const float* Uh1 = (const float*)d_in[11];
    const float* Uz1 = (const float*)d_in[12];
    float* out = (float*)d_out;

    cudaFuncSetAttribute(fused, cudaFuncAttributeMaxDynamicSharedMemorySize,
                         FUSED_SMEM);

    dim3 gg(MM / 64, HH / 64);
    gemm512<<<gg, 256>>>(x, Wh0, bh0, 0, FF);
    gemm512<<<gg, 256>>>(x, Wz0, bz0, 1, FF);
    fused<<<NC, 256, FUSED_SMEM>>>(Uh0, Uz0, Uh1, Uz1, Wh1, Wz1, bh1, bz1, out);
}

// round 17
// speedup vs baseline: 1.4324x; 1.2149x over previous
#include <cuda_runtime.h>
#include <math.h>

#define TT 1500
#define BB 16
#define FF 440
#define HH 512
#define MM (TT*BB)      // 24000
#define NC 128          // persistent CTAs (single wave)

typedef unsigned long long ull;

// ---------------- device scratch (no allocations allowed) -------------------
__device__ float g_wh0[MM*HH];
__device__ float g_wz0[MM*HH];
__device__ float g_h1buf[2*BB*HH];
__device__ float g_h2buf[2*BB*HH];
__device__ unsigned g_count;   // zero-init; monotonic arrivals
__device__ unsigned g_gen;     // zero-init; completed generations

// ---------------- helpers ----------------------------------------------------
__device__ __forceinline__ unsigned ld_acq(const unsigned* p) {
    unsigned v;
    asm volatile("ld.acquire.gpu.u32 %0, [%1];" : "=r"(v) : "l"(p) : "memory");
    return v;
}
__device__ __forceinline__ void st_rel(unsigned* p, unsigned v) {
    asm volatile("st.release.gpu.u32 [%0], %1;" :: "l"(p), "r"(v) : "memory");
}
__device__ __forceinline__ void fma2(ull &d, ull a, ull b) {
    asm("fma.rn.f32x2 %0, %1, %2, %0;" : "+l"(d) : "l"(a), "l"(b));
}
__device__ __forceinline__ void unpack2(ull v, float &lo, float &hi) {
    asm("mov.b64 {%0, %1}, %2;" : "=f"(lo), "=f"(hi) : "l"(v));
}

// fold-reduce 16 values over 32 lanes: every lane ends with the full 32-lane
// sum of v16[(lane>>1)&15].
__device__ __forceinline__ float warp_fold16(const float v16[16], int lane) {
    float v8[8];
    { bool hi = (lane & 16) != 0;
      #pragma unroll
      for (int i = 0; i < 8; ++i) {
          float s = hi ? v16[i] : v16[i+8];
          float k = hi ? v16[i+8] : v16[i];
          v8[i] = k + __shfl_xor_sync(0xffffffffu, s, 16); } }
    float v4[4];
    { bool hi = (lane & 8) != 0;
      #pragma unroll
      for (int i = 0; i < 4; ++i) {
          float s = hi ? v8[i] : v8[i+4];
          float k = hi ? v8[i+4] : v8[i];
          v4[i] = k + __shfl_xor_sync(0xffffffffu, s, 8); } }
    float v2[2];
    { bool hi = (lane & 4) != 0;
      #pragma unroll
      for (int i = 0; i < 2; ++i) {
          float s = hi ? v4[i] : v4[i+2];
          float k = hi ? v4[i+2] : v4[i];
          v2[i] = k + __shfl_xor_sync(0xffffffffu, s, 4); } }
    float v1;
    { bool hi = (lane & 2) != 0;
      float s = hi ? v2[0] : v2[1];
      float k = hi ? v2[1] : v2[0];
      v1 = k + __shfl_xor_sync(0xffffffffu, s, 2); }
    v1 += __shfl_xor_sync(0xffffffffu, v1, 1);
    return v1;
}

// ---------------- projection GEMM: C[M,512] = A[M,K] @ W[512,K]^T + bias ----
__global__ void __launch_bounds__(256) gemm512(
    const float* __restrict__ A,
    const float* __restrict__ W, const float* __restrict__ bias,
    int out_sel, int K)
{
    float* C = out_sel ? g_wz0 : g_wh0;

    __shared__ __align__(16) float As[8][64];
    __shared__ __align__(16) float Bs[8][64];

    int tid = threadIdx.x;
    int m0 = blockIdx.x * 64, n0 = blockIdx.y * 64;
    int lr = tid >> 2;
    int lk = (tid & 3) * 2;
    const float* ap = A + (size_t)(m0 + lr) * K + lk;
    const float* wp = W + (size_t)(n0 + lr) * K + lk;
    int ty = tid >> 4, tx = tid & 15;

    float acc[4][4] = {};
    int nkb = K / 8;
    for (int kb = 0; kb < nkb; ++kb) {
        float2 av = *(const float2*)ap;
        float2 wv = *(const float2*)wp;
        ap += 8; wp += 8;
        As[lk][lr] = av.x; As[lk+1][lr] = av.y;
        Bs[lk][lr] = wv.x; Bs[lk+1][lr] = wv.y;
        __syncthreads();
        #pragma unroll
        for (int k = 0; k < 8; ++k) {
            float4 a4 = *(const float4*)&As[k][ty*4];
            float4 b4 = *(const float4*)&Bs[k][tx*4];
            float a_[4] = {a4.x, a4.y, a4.z, a4.w};
            float b_[4] = {b4.x, b4.y, b4.z, b4.w};
            #pragma unroll
            for (int i = 0; i < 4; ++i)
                #pragma unroll
                for (int j = 0; j < 4; ++j)
                    acc[i][j] += a_[i] * b_[j];
        }
        __syncthreads();
    }
    #pragma unroll
    for (int i = 0; i < 4; ++i) {
        float4 o;
        o.x = acc[i][0] + bias[n0 + tx*4 + 0];
        o.y = acc[i][1] + bias[n0 + tx*4 + 1];
        o.z = acc[i][2] + bias[n0 + tx*4 + 2];
        o.w = acc[i][3] + bias[n0 + tx*4 + 3];
        *(float4*)&C[(size_t)(m0 + ty*4 + i) * HH + n0 + tx*4] = o;
    }
}

// ---------------- fused persistent 2-layer, merged dots ----------------------
// iter t: layer1 step t AND layer2 step t-1, single barrier per iter (R13
// protocol). Dots merged into ONE k-pass: h1[t-1] loads shared between U0-dots
// and W1-dots; W1·h1 and U1·h2 accumulate into one register set (their sum is
// all the layer-2 gates need) -> 32 accs, 2 folds, 128 LDS.64/thread.
// CTA owns columns j0..j0+3. Warp w: bg=w>>1 (4 batches), rg=w&1 (gate).
__global__ void __launch_bounds__(256, 1) fused(
    const float* __restrict__ Uh0, const float* __restrict__ Uz0,
    const float* __restrict__ Uh1, const float* __restrict__ Uz1,
    const float* __restrict__ Wh1, const float* __restrict__ Wz1,
    const float* __restrict__ bh1, const float* __restrict__ bz1,
    float* __restrict__ out)
{
    extern __shared__ float sm[];
    float* h1s = sm;                 // 8192 f : h1[t-1]
    float* h2s = sm + 8192;          // 8192 f : h2[t-2]
    float* w1s = sm + 16384;         // 4096 f : [gate][4 rows][512] Wz1/Wh1
    float* u1s = sm + 20480;         // 4096 f : [gate][4 rows][512] Uz1/Uh1
    float* sdA = sm + 24576;         // 128 f  : L1 dots [gate][b][r]
    float* sdP = sm + 24704;         // 128 f  : L2 combined dots
    __shared__ unsigned s_base;

    int tid = threadIdx.x, w = tid >> 5, lane = tid & 31;
    int bg = w >> 1, rg = w & 1;
    int j0 = blockIdx.x * 4;
    int k0 = lane * 2;

    if (tid == 0) s_base = ld_acq(&g_gen);

    // layer-1 U slice in registers
    const float* U0 = rg ? Uh0 : Uz0;
    ull U0r[4][8];
    #pragma unroll
    for (int r = 0; r < 4; ++r)
        #pragma unroll
        for (int i = 0; i < 8; ++i)
            U0r[r][i] = *(const ull*)&U0[(size_t)(j0 + r) * HH + k0 + 64*i];

    // layer-2 weight slices into smem (persistent)
    for (int q = tid; q < 1024; q += 256) {
        int g = q >> 9, r = (q >> 7) & 3, kk = (q & 127) * 4;
        const float* Wp = g ? Wh1 : Wz1;
        const float* Up = g ? Uh1 : Uz1;
        ((float4*)w1s)[q] = *(const float4*)&Wp[(size_t)(j0 + r) * HH + kk];
        ((float4*)u1s)[q] = *(const float4*)&Up[(size_t)(j0 + r) * HH + kk];
    }
    __syncthreads();
    unsigned base = s_base;

    int gb = tid >> 2, gr = tid & 3;     // gate threads: tid < 64
    float wzv = 0.f, whv = 0.f, bh1v = 0.f, bz1v = 0.f;
    int ob = gb * HH + j0 + gr;
    if (tid < 64) {
        wzv  = __ldcg(&g_wz0[ob]);
        whv  = __ldcg(&g_wh0[ob]);
        bz1v = bz1[j0 + gr];
        bh1v = bh1[j0 + gr];
    }

    const float* hb1 = h1s + (size_t)bg * 4 * HH;
    const float* hb2 = h2s + (size_t)bg * 4 * HH;
    const float* wb  = w1s + rg * 2048;
    const float* ub  = u1s + rg * 2048;

    for (int t = 0; t <= TT; ++t) {
        // ---- barrier wait (h1[t-1], h2[t-2] published by all CTAs) ----
        if (t > 0 && tid == 0) {
            unsigned tg = base + (unsigned)t;
            while ((int)(ld_acq(&g_gen) - tg) < 0) { }
        }
        __syncthreads();

        // ---- stage h1[t-1], h2[t-2] ----
        if (t == 0) {
            for (int f = tid; f < 2048; f += 256)
                ((float4*)h1s)[f] = make_float4(0.f,0.f,0.f,0.f);
        } else {
            const float4* s1 = (const float4*)(g_h1buf + (size_t)((t-1)&1) * BB * HH);
            #pragma unroll
            for (int q = 0; q < 8; ++q)
                ((float4*)h1s)[tid + q*256] = __ldcg(s1 + tid + q*256);
        }
        if (t <= 1) {
            for (int f = tid; f < 2048; f += 256)
                ((float4*)h2s)[f] = make_float4(0.f,0.f,0.f,0.f);
        } else {
            const float4* s2 = (const float4*)(g_h2buf + (size_t)(t&1) * BB * HH);
            #pragma unroll
            for (int q = 0; q < 8; ++q)
                ((float4*)h2s)[tid + q*256] = __ldcg(s2 + tid + q*256);
        }
        __syncthreads();

        // ---- merged dots: A = U0(rg)·h1 ; PQ = W1(rg)·h1 + U1(rg)·h2 ----
        ull accA[16], accPQ[16];
        #pragma unroll
        for (int j = 0; j < 16; ++j) { accA[j] = 0ull; accPQ[j] = 0ull; }
        #pragma unroll
        for (int i = 0; i < 8; ++i) {
            int k = k0 + 64*i;
            ull h10 = *(const ull*)&hb1[k];
            ull h11 = *(const ull*)&hb1[HH + k];
            ull h12 = *(const ull*)&hb1[2*HH + k];
            ull h13 = *(const ull*)&hb1[3*HH + k];
            ull h20 = *(const ull*)&hb2[k];
            ull h21 = *(const ull*)&hb2[HH + k];
            ull h22 = *(const ull*)&hb2[2*HH + k];
            ull h23 = *(const ull*)&hb2[3*HH + k];
            ull wv0 = *(const ull*)&wb[k];
            ull wv1 = *(const ull*)&wb[HH + k];
            ull wv2 = *(const ull*)&wb[2*HH + k];
            ull wv3 = *(const ull*)&wb[3*HH + k];
            ull uv0 = *(const ull*)&ub[k];
            ull uv1 = *(const ull*)&ub[HH + k];
            ull uv2 = *(const ull*)&ub[2*HH + k];
            ull uv3 = *(const ull*)&ub[3*HH + k];
            // A dots (U0 in registers)
            fma2(accA[0],  U0r[0][i], h10); fma2(accA[1],  U0r[0][i], h11);
            fma2(accA[2],  U0r[0][i], h12); fma2(accA[3],  U0r[0][i], h13);
            fma2(accA[4],  U0r[1][i], h10); fma2(accA[5],  U0r[1][i], h11);
            fma2(accA[6],  U0r[1][i], h12); fma2(accA[7],  U0r[1][i], h13);
            fma2(accA[8],  U0r[2][i], h10); fma2(accA[9],  U0r[2][i], h11);
            fma2(accA[10], U0r[2][i], h12); fma2(accA[11], U0r[2][i], h13);
            fma2(accA[12], U0r[3][i], h10); fma2(accA[13], U0r[3][i], h11);
            fma2(accA[14], U0r[3][i], h12); fma2(accA[15], U0r[3][i], h13);
            // PQ dots: W1·h1
            fma2(accPQ[0],  wv0, h10); fma2(accPQ[1],  wv0, h11);
            fma2(accPQ[2],  wv0, h12); fma2(accPQ[3],  wv0, h13);
            fma2(accPQ[4],  wv1, h10); fma2(accPQ[5],  wv1, h11);
            fma2(accPQ[6],  wv1, h12); fma2(accPQ[7],  wv1, h13);
            fma2(accPQ[8],  wv2, h10); fma2(accPQ[9],  wv2, h11);
            fma2(accPQ[10], wv2, h12); fma2(accPQ[11], wv2, h13);
            fma2(accPQ[12], wv3, h10); fma2(accPQ[13], wv3, h11);
            fma2(accPQ[14], wv3, h12); fma2(accPQ[15], wv3, h13);
            // PQ dots: + U1·h2
            fma2(accPQ[0],  uv0, h20); fma2(accPQ[1],  uv0, h21);
            fma2(accPQ[2],  uv0, h22); fma2(accPQ[3],  uv0, h23);
            fma2(accPQ[4],  uv1, h20); fma2(accPQ[5],  uv1, h21);
            fma2(accPQ[6],  uv1, h22); fma2(accPQ[7],  uv1, h23);
            fma2(accPQ[8],  uv2, h20); fma2(accPQ[9],  uv2, h21);
            fma2(accPQ[10], uv2, h22); fma2(accPQ[11], uv2, h23);
            fma2(accPQ[12], uv3, h20); fma2(accPQ[13], uv3, h21);
            fma2(accPQ[14], uv3, h22); fma2(accPQ[15], uv3, h23);
        }
        {
            float val[16];
            #pragma unroll
            for (int j = 0; j < 16; ++j) {
                float lo, hi; unpack2(accA[j], lo, hi);
                val[j] = lo + hi;            // index j = r*4 + b
            }
            float s = warp_fold16(val, lane);
            int v = (lane >> 1) & 15;
            if (!(lane & 1))
                sdA[rg*64 + (bg*4 + (v&3))*4 + (v>>2)] = s;
        }
        {
            float val[16];
            #pragma unroll
            for (int j = 0; j < 16; ++j) {
                float lo, hi; unpack2(accPQ[j], lo, hi);
                val[j] = lo + hi;
            }
            float s = warp_fold16(val, lane);
            int v = (lane >> 1) & 15;
            if (!(lane & 1))
                sdP[rg*64 + (bg*4 + (v&3))*4 + (v>>2)] = s;
        }
        __syncthreads();

        // ---- gate phase: layer1 step t, layer2 step t-1 ----
        if (tid < 64) {
            if (t < TT) {
                float z  = 1.f / (1.f + __expf(-(wzv + sdA[gb*4 + gr])));
                float hc = whv + sdA[64 + gb*4 + gr];
                hc = hc > 0.f ? hc : 0.f;
                float h1n = z * h1s[gb*HH + j0 + gr] + (1.f - z) * hc;
                g_h1buf[(size_t)(t&1) * BB * HH + gb*HH + j0 + gr] = h1n;
            }
            if (t >= 1) {
                float zp  = 1.f / (1.f + __expf(-(bz1v + sdP[gb*4 + gr])));
                float hcp = bh1v + sdP[64 + gb*4 + gr];
                hcp = hcp > 0.f ? hcp : 0.f;
                float h2n = zp * h2s[gb*HH + j0 + gr] + (1.f - zp) * hcp;
                g_h2buf[(size_t)((t-1)&1) * BB * HH + gb*HH + j0 + gr] = h2n;
                out[(size_t)((t-1)*BB + gb) * HH + j0 + gr] = h2n;
            }
            if (t + 1 < TT) {            // prefetch next projections
                ob += BB * HH;
                wzv = __ldcg(&g_wz0[ob]);
                whv = __ldcg(&g_wh0[ob]);
            }
        }
        __syncthreads();

        // ---- arrive: atomic counter, last publishes generation ----
        if (t < TT && tid == 0) {
            __threadfence();
            unsigned old = atomicAdd(&g_count, 1u);
            if (old + 1u == (base + (unsigned)t + 1u) * NC)
                st_rel(&g_gen, base + (unsigned)t + 1u);
        }
    }
}

// ---------------- launch ----------------------------------------------------
#define FUSED_SMEM ((24832) * 4)

extern "C" void kernel_launch(void* const* d_in, const int* in_sizes, int n_in,
                              void* d_out, int out_size) {
    const float* x   = (const float*)d_in[0];
    const float* Wh0 = (const float*)d_in[1];
    const float* bh0 = (const float*)d_in[2];
    const float* Wz0 = (const float*)d_in[3];
    const float* bz0 = (const float*)d_in[4];
    const float* Uh0 = (const float*)d_in[5];
    const float* Uz0 = (const float*)d_in[6];
    const float* Wh1 = (const float*)d_in[7];
    const float* bh1 = (const float*)d_in[8];
    const float* Wz1 = (const float*)d_in[9];
    const float* bz1 = (const float*)d_in[10];
    const float* Uh1 = (const float*)d_in[11];
    const float* Uz1 = (const float*)d_in[12];
    float* out = (float*)d_out;

    cudaFuncSetAttribute(fused, cudaFuncAttributeMaxDynamicSharedMemorySize,
                         FUSED_SMEM);

    dim3 gg(MM / 64, HH / 64);
    gemm512<<<gg, 256>>>(x, Wh0, bh0, 0, FF);
    gemm512<<<gg, 256>>>(x, Wz0, bz0, 1, FF);
    fused<<<NC, 256, FUSED_SMEM>>>(Uh0, Uz0, Uh1, Uz1, Wh1, Wz1, bh1, bz1, out);
}